// round 1
// baseline (speedup 1.0000x reference)
#include <cuda_runtime.h>
#include <math.h>

// ---------------------------------------------------------------------------
// Problem constants
// ---------------------------------------------------------------------------
#define Bz  32
#define Sz  512
#define Dz  512
#define Hz  8
#define HDz 64
#define FFz 2048
#define Lz  6
#define INz 32
#define OUTz 3
#define BS  (Bz * Sz)          // 16384 tokens

// ---------------------------------------------------------------------------
// Scratch buffers (static device globals; no runtime allocation)
// ---------------------------------------------------------------------------
__device__ float g_h[BS * Dz];          // residual stream (B*S, D)
__device__ float g_qkv[BS * 3 * Dz];    // fused qkv activations
__device__ float g_attno[BS * Dz];      // attention output (pre out-proj)
__device__ float g_ff[BS * FFz];        // ff intermediate
__device__ float g_res[BS * Dz];        // projection outputs (residual branch)

// ---------------------------------------------------------------------------
// Helpers
// ---------------------------------------------------------------------------
__device__ __forceinline__ float gelu_exact(float x) {
    return 0.5f * x * (1.0f + erff(x * 0.70710678118654752f));
}

__device__ __forceinline__ float block_reduce_sum_256(float v, float* red) {
    int tid = threadIdx.x;
    red[tid] = v;
    __syncthreads();
    #pragma unroll
    for (int s = 128; s > 0; s >>= 1) {
        if (tid < s) red[tid] += red[tid + s];
        __syncthreads();
    }
    float r = red[0];
    __syncthreads();
    return r;
}

// ---------------------------------------------------------------------------
// Embed: h = gelu(LN(x @ w_in + b_in)) + PE     one block per token, 256 thr
// ---------------------------------------------------------------------------
__global__ void embed_kernel(const float* __restrict__ x,
                             const float* __restrict__ w_in,
                             const float* __restrict__ b_in,
                             const float* __restrict__ g_in,
                             const float* __restrict__ be_in) {
    int t = blockIdx.x;              // token index = b*S + s
    int tid = threadIdx.x;
    __shared__ float xrow[INz];
    __shared__ float vals[Dz];
    __shared__ float red[256];

    if (tid < INz) xrow[tid] = x[t * INz + tid];
    __syncthreads();

    #pragma unroll
    for (int p = 0; p < 2; p++) {
        int c = tid + p * 256;
        float acc = b_in[c];
        #pragma unroll
        for (int k = 0; k < INz; k++) acc += xrow[k] * w_in[k * Dz + c];
        vals[c] = acc;
    }
    __syncthreads();

    float v0 = vals[tid], v1 = vals[tid + 256];
    float mu = block_reduce_sum_256(v0 + v1, red) * (1.0f / Dz);
    float d0 = v0 - mu, d1 = v1 - mu;
    float var = block_reduce_sum_256(d0 * d0 + d1 * d1, red) * (1.0f / Dz);
    float inv = rsqrtf(var + 1e-5f);

    int s = t % Sz;
    float pos = (float)s;
    const float kLog = 9.210340371976184f / (float)Dz;   // ln(10000)/D

    #pragma unroll
    for (int p = 0; p < 2; p++) {
        int c = tid + p * 256;
        float d = (p == 0 ? d0 : d1);
        float y = d * inv * g_in[c] + be_in[c];
        y = gelu_exact(y);
        int i2 = c & ~1;
        float div = __expf(-(float)i2 * kLog);
        float ang = pos * div;
        y += (c & 1) ? cosf(ang) : sinf(ang);
        g_h[t * Dz + c] = y;
    }
}

// ---------------------------------------------------------------------------
// Tiled SGEMM:  C[M,N] = act(A[M,K] @ W[K,N] + bias)
// BM=BN=64, BK=16, 256 threads, 4x4 micro-tile. M,N%64==0, K%16==0 assumed.
// ACT: 0 = none, 1 = exact gelu
// ---------------------------------------------------------------------------
#define GBM 64
#define GBN 64
#define GBK 16

template <int ACT>
__global__ void sgemm_kernel(const float* __restrict__ A,
                             const float* __restrict__ W,
                             const float* __restrict__ bias,
                             float* __restrict__ C,
                             int M, int N, int K) {
    __shared__ float As[GBK][GBM];
    __shared__ float Bs[GBK][GBN];

    int tid = threadIdx.x;
    int tx = tid & 15;          // 0..15 -> col group
    int ty = tid >> 4;          // 0..15 -> row group
    int rowBase = blockIdx.y * GBM;
    int colBase = blockIdx.x * GBN;

    // A tile load: 64 rows x 16 k; one float4 per thread
    int ar = tid >> 2;              // 0..63
    int ac = (tid & 3) * 4;         // 0,4,8,12
    // B tile load: 16 k x 64 cols; one float4 per thread
    int br = tid >> 4;              // 0..15
    int bc = (tid & 15) * 4;        // 0..60

    const float* Aptr = A + (size_t)(rowBase + ar) * K + ac;
    const float* Wptr = W + (size_t)br * N + colBase + bc;

    float acc[4][4] = {};

    for (int k0 = 0; k0 < K; k0 += GBK) {
        float4 a4 = *(const float4*)Aptr;
        Aptr += GBK;
        As[ac + 0][ar] = a4.x;
        As[ac + 1][ar] = a4.y;
        As[ac + 2][ar] = a4.z;
        As[ac + 3][ar] = a4.w;
        *(float4*)(&Bs[br][bc]) = *(const float4*)Wptr;
        Wptr += (size_t)GBK * N;
        __syncthreads();

        #pragma unroll
        for (int k = 0; k < GBK; k++) {
            float a[4], b[4];
            #pragma unroll
            for (int i = 0; i < 4; i++) a[i] = As[k][ty * 4 + i];
            #pragma unroll
            for (int j = 0; j < 4; j++) b[j] = Bs[k][tx * 4 + j];
            #pragma unroll
            for (int i = 0; i < 4; i++)
                #pragma unroll
                for (int j = 0; j < 4; j++)
                    acc[i][j] += a[i] * b[j];
        }
        __syncthreads();
    }

    #pragma unroll
    for (int i = 0; i < 4; i++) {
        int row = rowBase + ty * 4 + i;
        #pragma unroll
        for (int j = 0; j < 4; j++) {
            int col = colBase + tx * 4 + j;
            float v = acc[i][j] + bias[col];
            if (ACT == 1) v = gelu_exact(v);
            C[(size_t)row * N + col] = v;
        }
    }
}

// ---------------------------------------------------------------------------
// Attention: one block per (query row i, b*H+h). 128 threads.
// qkv layout per token: [q(512) | k(512) | v(512)], head h at offset h*64.
// ---------------------------------------------------------------------------
__global__ void attn_kernel() {
    int i  = blockIdx.x;                 // query position
    int bh = blockIdx.y;
    int b  = bh / Hz;
    int h  = bh % Hz;
    int tid = threadIdx.x;

    __shared__ float q[HDz];
    __shared__ float sc[Sz];
    __shared__ float red[128];

    const float* qp = g_qkv + ((size_t)(b * Sz + i) * 3 * Dz) + h * HDz;
    if (tid < HDz) q[tid] = qp[tid];
    __syncthreads();

    // scores
    for (int j = tid; j <= i; j += 128) {
        const float* kp = g_qkv + ((size_t)(b * Sz + j) * 3 * Dz) + Dz + h * HDz;
        float acc = 0.f;
        #pragma unroll
        for (int d4 = 0; d4 < HDz; d4 += 4) {
            float4 kv = *(const float4*)(kp + d4);
            acc += q[d4 + 0] * kv.x + q[d4 + 1] * kv.y +
                   q[d4 + 2] * kv.z + q[d4 + 3] * kv.w;
        }
        sc[j] = acc * 0.125f;            // 1/sqrt(64)
    }
    __syncthreads();

    // softmax (max then exp-sum)
    float m = -1e30f;
    for (int j = tid; j <= i; j += 128) m = fmaxf(m, sc[j]);
    red[tid] = m;
    __syncthreads();
    #pragma unroll
    for (int s = 64; s > 0; s >>= 1) {
        if (tid < s) red[tid] = fmaxf(red[tid], red[tid + s]);
        __syncthreads();
    }
    m = red[0];
    __syncthreads();

    float ps = 0.f;
    for (int j = tid; j <= i; j += 128) {
        float e = __expf(sc[j] - m);
        sc[j] = e;
        ps += e;
    }
    red[tid] = ps;
    __syncthreads();
    #pragma unroll
    for (int s = 64; s > 0; s >>= 1) {
        if (tid < s) red[tid] += red[tid + s];
        __syncthreads();
    }
    float denom = red[0];
    __syncthreads();

    // AV: 2-way split over j, 64 lanes over d
    int d = tid & 63;
    int half = tid >> 6;
    float acc = 0.f;
    for (int j = half; j <= i; j += 2) {
        const float* vp = g_qkv + ((size_t)(b * Sz + j) * 3 * Dz) + 2 * Dz + h * HDz;
        acc += sc[j] * vp[d];
    }
    red[tid] = acc;
    __syncthreads();
    if (tid < 64) {
        float o = (red[tid] + red[tid + 64]) / denom;
        g_attno[(size_t)(b * Sz + i) * Dz + h * HDz + d] = o;
    }
}

// ---------------------------------------------------------------------------
// Residual + LayerNorm: h = LN(h + r) * g + be   (in-place on g_h)
// ---------------------------------------------------------------------------
__global__ void residual_ln_kernel(const float* __restrict__ r,
                                   const float* __restrict__ g,
                                   const float* __restrict__ be) {
    int t = blockIdx.x;
    int tid = threadIdx.x;
    __shared__ float red[256];

    float v0 = g_h[(size_t)t * Dz + tid]       + r[(size_t)t * Dz + tid];
    float v1 = g_h[(size_t)t * Dz + tid + 256] + r[(size_t)t * Dz + tid + 256];

    float mu = block_reduce_sum_256(v0 + v1, red) * (1.0f / Dz);
    float d0 = v0 - mu, d1 = v1 - mu;
    float var = block_reduce_sum_256(d0 * d0 + d1 * d1, red) * (1.0f / Dz);
    float inv = rsqrtf(var + 1e-5f);

    g_h[(size_t)t * Dz + tid]       = d0 * inv * g[tid]       + be[tid];
    g_h[(size_t)t * Dz + tid + 256] = d1 * inv * g[tid + 256] + be[tid + 256];
}

// ---------------------------------------------------------------------------
// Head: logits = gelu(h_last @ w_h1 + b_h1) @ w_h2 + b_h2   (last token only)
// ---------------------------------------------------------------------------
__global__ void head_kernel(const float* __restrict__ w_h1,
                            const float* __restrict__ b_h1,
                            const float* __restrict__ w_h2,
                            const float* __restrict__ b_h2,
                            float* __restrict__ out) {
    int b = blockIdx.x;
    int tid = threadIdx.x;
    int t = b * Sz + (Sz - 1);
    __shared__ float hrow[Dz];
    __shared__ float mid[Dz / 2];

    hrow[tid]       = g_h[(size_t)t * Dz + tid];
    hrow[tid + 256] = g_h[(size_t)t * Dz + tid + 256];
    __syncthreads();

    float acc = b_h1[tid];
    #pragma unroll 8
    for (int k = 0; k < Dz; k++) acc += hrow[k] * w_h1[k * (Dz / 2) + tid];
    mid[tid] = gelu_exact(acc);
    __syncthreads();

    if (tid < OUTz) {
        float o = b_h2[tid];
        for (int j = 0; j < Dz / 2; j++) o += mid[j] * w_h2[j * OUTz + tid];
        out[b * OUTz + tid] = o;
    }
}

// ---------------------------------------------------------------------------
// Launch
// ---------------------------------------------------------------------------
extern "C" void kernel_launch(void* const* d_in, const int* in_sizes, int n_in,
                              void* d_out, int out_size) {
    const float* x     = (const float*)d_in[0];
    const float* w_in  = (const float*)d_in[1];
    const float* b_in  = (const float*)d_in[2];
    const float* g_in  = (const float*)d_in[3];
    const float* be_in = (const float*)d_in[4];
    const float* w_qkv = (const float*)d_in[5];
    const float* b_qkv = (const float*)d_in[6];
    const float* w_out = (const float*)d_in[7];
    const float* b_out = (const float*)d_in[8];
    const float* g1    = (const float*)d_in[9];
    const float* be1   = (const float*)d_in[10];
    const float* w_ff1 = (const float*)d_in[11];
    const float* b_ff1 = (const float*)d_in[12];
    const float* w_ff2 = (const float*)d_in[13];
    const float* b_ff2 = (const float*)d_in[14];
    const float* g2    = (const float*)d_in[15];
    const float* be2   = (const float*)d_in[16];
    const float* w_h1  = (const float*)d_in[17];
    const float* b_h1  = (const float*)d_in[18];
    const float* w_h2  = (const float*)d_in[19];
    const float* b_h2  = (const float*)d_in[20];
    float* out = (float*)d_out;

    static float *p_h = nullptr, *p_qkv = nullptr, *p_attno = nullptr,
                 *p_ff = nullptr, *p_res = nullptr;
    if (!p_h) {
        cudaGetSymbolAddress((void**)&p_h, g_h);
        cudaGetSymbolAddress((void**)&p_qkv, g_qkv);
        cudaGetSymbolAddress((void**)&p_attno, g_attno);
        cudaGetSymbolAddress((void**)&p_ff, g_ff);
        cudaGetSymbolAddress((void**)&p_res, g_res);
    }

    // Embed + LN + gelu + positional encoding
    embed_kernel<<<BS, 256>>>(x, w_in, b_in, g_in, be_in);

    for (int l = 0; l < Lz; l++) {
        const float* wqkv_l = w_qkv + (size_t)l * Dz * 3 * Dz;
        const float* bqkv_l = b_qkv + (size_t)l * 3 * Dz;
        const float* wout_l = w_out + (size_t)l * Dz * Dz;
        const float* bout_l = b_out + (size_t)l * Dz;
        const float* wff1_l = w_ff1 + (size_t)l * Dz * FFz;
        const float* bff1_l = b_ff1 + (size_t)l * FFz;
        const float* wff2_l = w_ff2 + (size_t)l * FFz * Dz;
        const float* bff2_l = b_ff2 + (size_t)l * Dz;

        // qkv = h @ w_qkv + b
        sgemm_kernel<0><<<dim3((3 * Dz) / GBN, BS / GBM), 256>>>(
            p_h, wqkv_l, bqkv_l, p_qkv, BS, 3 * Dz, Dz);

        // attention
        attn_kernel<<<dim3(Sz, Bz * Hz), 128>>>();

        // out projection
        sgemm_kernel<0><<<dim3(Dz / GBN, BS / GBM), 256>>>(
            p_attno, wout_l, bout_l, p_res, BS, Dz, Dz);

        // h = LN(h + o)
        residual_ln_kernel<<<BS, 256>>>(p_res, g1 + (size_t)l * Dz,
                                        be1 + (size_t)l * Dz);

        // ff1 with gelu
        sgemm_kernel<1><<<dim3(FFz / GBN, BS / GBM), 256>>>(
            p_h, wff1_l, bff1_l, p_ff, BS, FFz, Dz);

        // ff2
        sgemm_kernel<0><<<dim3(Dz / GBN, BS / GBM), 256>>>(
            p_ff, wff2_l, bff2_l, p_res, BS, Dz, FFz);

        // h = LN(h + f)
        residual_ln_kernel<<<BS, 256>>>(p_res, g2 + (size_t)l * Dz,
                                        be2 + (size_t)l * Dz);
    }

    // head on last tokens
    head_kernel<<<Bz, 256>>>(w_h1, b_h1, w_h2, b_h2, out);
}

// round 2
// speedup vs baseline: 3.7908x; 3.7908x over previous
#include <cuda_runtime.h>
#include <math.h>
#include <stdint.h>

// ---------------------------------------------------------------------------
// Problem constants
// ---------------------------------------------------------------------------
#define Bz  32
#define Sz  512
#define Dz  512
#define Hz  8
#define HDz 64
#define FFz 2048
#define Lz  6
#define INz 32
#define OUTz 3
#define BS  (Bz * Sz)          // 16384 tokens

// ---------------------------------------------------------------------------
// Scratch buffers (static device globals; no runtime allocation)
// ---------------------------------------------------------------------------
__device__ float g_h[BS * Dz];          // residual stream (B*S, D)
__device__ float g_qkv[BS * 3 * Dz];    // fused qkv activations
__device__ float g_attno[BS * Dz];      // attention output (pre out-proj)
__device__ float g_ff[BS * FFz];        // ff intermediate
__device__ float g_res[BS * Dz];        // projection outputs (residual branch)

// ---------------------------------------------------------------------------
// Helpers
// ---------------------------------------------------------------------------
__device__ __forceinline__ float gelu_exact(float x) {
    return 0.5f * x * (1.0f + erff(x * 0.70710678118654752f));
}

__device__ __forceinline__ uint32_t f2tf32(float x) {
    uint32_t u;
    asm("cvt.rna.tf32.f32 %0, %1;" : "=r"(u) : "f"(x));
    return u;
}

__device__ __forceinline__ float block_reduce_sum_256(float v, float* red) {
    int tid = threadIdx.x;
    red[tid] = v;
    __syncthreads();
    #pragma unroll
    for (int s = 128; s > 0; s >>= 1) {
        if (tid < s) red[tid] += red[tid + s];
        __syncthreads();
    }
    float r = red[0];
    __syncthreads();
    return r;
}

// ---------------------------------------------------------------------------
// Embed: h = gelu(LN(x @ w_in + b_in)) + PE     one block per token, 256 thr
// ---------------------------------------------------------------------------
__global__ void embed_kernel(const float* __restrict__ x,
                             const float* __restrict__ w_in,
                             const float* __restrict__ b_in,
                             const float* __restrict__ g_in,
                             const float* __restrict__ be_in) {
    int t = blockIdx.x;
    int tid = threadIdx.x;
    __shared__ float xrow[INz];
    __shared__ float vals[Dz];
    __shared__ float red[256];

    if (tid < INz) xrow[tid] = x[t * INz + tid];
    __syncthreads();

    #pragma unroll
    for (int p = 0; p < 2; p++) {
        int c = tid + p * 256;
        float acc = b_in[c];
        #pragma unroll
        for (int k = 0; k < INz; k++) acc += xrow[k] * w_in[k * Dz + c];
        vals[c] = acc;
    }
    __syncthreads();

    float v0 = vals[tid], v1 = vals[tid + 256];
    float mu = block_reduce_sum_256(v0 + v1, red) * (1.0f / Dz);
    float d0 = v0 - mu, d1 = v1 - mu;
    float var = block_reduce_sum_256(d0 * d0 + d1 * d1, red) * (1.0f / Dz);
    float inv = rsqrtf(var + 1e-5f);

    int s = t % Sz;
    float pos = (float)s;
    const float kLog = 9.210340371976184f / (float)Dz;   // ln(10000)/D

    #pragma unroll
    for (int p = 0; p < 2; p++) {
        int c = tid + p * 256;
        float d = (p == 0 ? d0 : d1);
        float y = d * inv * g_in[c] + be_in[c];
        y = gelu_exact(y);
        int i2 = c & ~1;
        float div = __expf(-(float)i2 * kLog);
        float ang = pos * div;
        y += (c & 1) ? cosf(ang) : sinf(ang);
        g_h[t * Dz + c] = y;
    }
}

// ---------------------------------------------------------------------------
// TF32 tensor-core GEMM: C[M,N] = act(A[M,K] @ W[K,N] + bias)
// 128x128x16 CTA tile, 256 threads (8 warps), each warp 64x32 via m16n8k8.
// ACT: 0 = none, 1 = exact gelu
// ---------------------------------------------------------------------------
#define TBM 128
#define TBN 128
#define TBK 16
#define SST 136   // smem row stride (floats): 8k'+m' -> conflict-free frags

template <int ACT>
__global__ __launch_bounds__(256, 2)
void sgemm_tc(const float* __restrict__ A,
              const float* __restrict__ W,
              const float* __restrict__ bias,
              float* __restrict__ C,
              int M, int N, int K) {
    __shared__ float As[TBK * SST];   // [k][m]
    __shared__ float Bs[TBK * SST];   // [k][n]

    int tid = threadIdx.x;
    int lane = tid & 31;
    int wid = tid >> 5;
    int wm = wid >> 2;                // 0..1  -> 64 rows
    int wn = wid & 3;                 // 0..3  -> 32 cols
    int qk = lane & 3;                // frag k index
    int qr = lane >> 2;               // frag row/col index (0..7)

    int rowBase = blockIdx.y * TBM;
    int colBase = blockIdx.x * TBN;

    // A staging: thread loads rows r and r+64, 4 k's
    int ar = tid >> 2;
    int ak = (tid & 3) << 2;
    const float* Ap0 = A + (size_t)(rowBase + ar) * K + ak;
    const float* Ap1 = A + (size_t)(rowBase + ar + 64) * K + ak;
    // B staging: thread loads k row kb, cols nb and nb+64
    int kb = tid >> 4;
    int nb = (tid & 15) << 2;
    const float* Wp = W + (size_t)kb * N + colBase + nb;

    float acc[2 == 2 ? 4 : 4][4][4];
    #pragma unroll
    for (int i = 0; i < 4; i++)
        #pragma unroll
        for (int j = 0; j < 4; j++)
            #pragma unroll
            for (int c = 0; c < 4; c++) acc[i][j][c] = 0.f;

    for (int k0 = 0; k0 < K; k0 += TBK) {
        float4 a0 = *(const float4*)Ap0;
        float4 a1 = *(const float4*)Ap1;
        float4 b0 = *(const float4*)Wp;
        float4 b1 = *(const float4*)(Wp + 64);
        Ap0 += TBK; Ap1 += TBK; Wp += (size_t)TBK * N;

        As[(ak + 0) * SST + ar] = __uint_as_float(f2tf32(a0.x));
        As[(ak + 1) * SST + ar] = __uint_as_float(f2tf32(a0.y));
        As[(ak + 2) * SST + ar] = __uint_as_float(f2tf32(a0.z));
        As[(ak + 3) * SST + ar] = __uint_as_float(f2tf32(a0.w));
        As[(ak + 0) * SST + ar + 64] = __uint_as_float(f2tf32(a1.x));
        As[(ak + 1) * SST + ar + 64] = __uint_as_float(f2tf32(a1.y));
        As[(ak + 2) * SST + ar + 64] = __uint_as_float(f2tf32(a1.z));
        As[(ak + 3) * SST + ar + 64] = __uint_as_float(f2tf32(a1.w));

        float4 tb0, tb1;
        tb0.x = __uint_as_float(f2tf32(b0.x));
        tb0.y = __uint_as_float(f2tf32(b0.y));
        tb0.z = __uint_as_float(f2tf32(b0.z));
        tb0.w = __uint_as_float(f2tf32(b0.w));
        tb1.x = __uint_as_float(f2tf32(b1.x));
        tb1.y = __uint_as_float(f2tf32(b1.y));
        tb1.z = __uint_as_float(f2tf32(b1.z));
        tb1.w = __uint_as_float(f2tf32(b1.w));
        *(float4*)&Bs[kb * SST + nb] = tb0;
        *(float4*)&Bs[kb * SST + nb + 64] = tb1;
        __syncthreads();

        #pragma unroll
        for (int ks = 0; ks < TBK; ks += 8) {
            uint32_t af[4][4], bf[4][2];
            #pragma unroll
            for (int mt = 0; mt < 4; mt++) {
                int mb = wm * 64 + mt * 16 + qr;
                af[mt][0] = __float_as_uint(As[(ks + qk) * SST + mb]);
                af[mt][1] = __float_as_uint(As[(ks + qk) * SST + mb + 8]);
                af[mt][2] = __float_as_uint(As[(ks + qk + 4) * SST + mb]);
                af[mt][3] = __float_as_uint(As[(ks + qk + 4) * SST + mb + 8]);
            }
            #pragma unroll
            for (int nt = 0; nt < 4; nt++) {
                int nbb = wn * 32 + nt * 8 + qr;
                bf[nt][0] = __float_as_uint(Bs[(ks + qk) * SST + nbb]);
                bf[nt][1] = __float_as_uint(Bs[(ks + qk + 4) * SST + nbb]);
            }
            #pragma unroll
            for (int mt = 0; mt < 4; mt++)
                #pragma unroll
                for (int nt = 0; nt < 4; nt++) {
                    asm volatile(
                        "mma.sync.aligned.m16n8k8.row.col.f32.tf32.tf32.f32 "
                        "{%0,%1,%2,%3},{%4,%5,%6,%7},{%8,%9},{%0,%1,%2,%3};"
                        : "+f"(acc[mt][nt][0]), "+f"(acc[mt][nt][1]),
                          "+f"(acc[mt][nt][2]), "+f"(acc[mt][nt][3])
                        : "r"(af[mt][0]), "r"(af[mt][1]),
                          "r"(af[mt][2]), "r"(af[mt][3]),
                          "r"(bf[nt][0]), "r"(bf[nt][1]));
                }
        }
        __syncthreads();
    }

    // Epilogue
    #pragma unroll
    for (int mt = 0; mt < 4; mt++) {
        int row0 = rowBase + wm * 64 + mt * 16 + qr;
        #pragma unroll
        for (int nt = 0; nt < 4; nt++) {
            int col0 = colBase + wn * 32 + nt * 8 + 2 * qk;
            float bia0 = bias[col0], bia1 = bias[col0 + 1];
            float v0 = acc[mt][nt][0] + bia0;
            float v1 = acc[mt][nt][1] + bia1;
            float v2 = acc[mt][nt][2] + bia0;
            float v3 = acc[mt][nt][3] + bia1;
            if (ACT == 1) {
                v0 = gelu_exact(v0); v1 = gelu_exact(v1);
                v2 = gelu_exact(v2); v3 = gelu_exact(v3);
            }
            *(float2*)&C[(size_t)row0 * N + col0] = make_float2(v0, v1);
            *(float2*)&C[(size_t)(row0 + 8) * N + col0] = make_float2(v2, v3);
        }
    }
}

// ---------------------------------------------------------------------------
// Flash-style attention. Block = (i-tile of 64 queries, b*H+h). 256 threads.
// Thread (rgrp=tid/16, cgrp=tid%16) owns rows rgrp*4+{0..3}, cols cgrp*4+{0..3}.
// smem: Qs[64][64], Kt[64][64] (d-major, aliased by P after scores), Vs[64][64].
// ---------------------------------------------------------------------------
__global__ __launch_bounds__(256)
void attn_flash_kernel() {
    __shared__ float Qs[64 * 64];
    __shared__ float KtPs[64 * 64];   // K transposed [d][j]; later P [r][j]
    __shared__ float Vs[64 * 64];     // [j][d]

    int itile = blockIdx.x;
    int bh = blockIdx.y;
    int b = bh / Hz;
    int h = bh % Hz;
    int tid = threadIdx.x;
    int rgrp = tid >> 4;              // 0..15
    int cgrp = tid & 15;              // 0..15

    size_t tokBase = (size_t)b * Sz;
    int i0 = itile * 64;

    // Load Q tile (fp32)
    #pragma unroll
    for (int it = 0; it < 4; it++) {
        int idx = tid + it * 256;
        int r = idx >> 4;
        int dq = (idx & 15) << 2;
        const float4 q4 = *(const float4*)(g_qkv +
            (tokBase + i0 + r) * (3 * Dz) + h * HDz + dq);
        *(float4*)&Qs[r * 64 + dq] = q4;
    }

    float m[4], l[4], o[4][4];
    #pragma unroll
    for (int ri = 0; ri < 4; ri++) {
        m[ri] = -1e30f; l[ri] = 0.f;
        #pragma unroll
        for (int dc = 0; dc < 4; dc++) o[ri][dc] = 0.f;
    }

    for (int jt = 0; jt <= itile; jt++) {
        int j0 = jt * 64;
        __syncthreads();   // prior P/V reads done before overwrite

        // Load K (transposed into [d][j]) and V ([j][d])
        #pragma unroll
        for (int it = 0; it < 4; it++) {
            int idx = tid + it * 256;
            int j = idx >> 4;
            int dq = (idx & 15) << 2;
            const float* base = g_qkv + (tokBase + j0 + j) * (3 * Dz) + h * HDz;
            float4 k4 = *(const float4*)(base + Dz + dq);
            float4 v4 = *(const float4*)(base + 2 * Dz + dq);
            KtPs[(dq + 0) * 64 + j] = k4.x;
            KtPs[(dq + 1) * 64 + j] = k4.y;
            KtPs[(dq + 2) * 64 + j] = k4.z;
            KtPs[(dq + 3) * 64 + j] = k4.w;
            *(float4*)&Vs[j * 64 + dq] = v4;
        }
        __syncthreads();

        // Scores S = Q K^T * scale  (4x4 per thread)
        float s[4][4];
        #pragma unroll
        for (int ri = 0; ri < 4; ri++)
            #pragma unroll
            for (int jj = 0; jj < 4; jj++) s[ri][jj] = 0.f;

        for (int d0 = 0; d0 < 64; d0 += 4) {
            float4 q4[4];
            #pragma unroll
            for (int ri = 0; ri < 4; ri++)
                q4[ri] = *(const float4*)&Qs[(rgrp * 4 + ri) * 64 + d0];
            #pragma unroll
            for (int dd = 0; dd < 4; dd++) {
                float4 k4 = *(const float4*)&KtPs[(d0 + dd) * 64 + cgrp * 4];
                #pragma unroll
                for (int ri = 0; ri < 4; ri++) {
                    float q = (dd == 0) ? q4[ri].x : (dd == 1) ? q4[ri].y
                            : (dd == 2) ? q4[ri].z : q4[ri].w;
                    s[ri][0] += q * k4.x;
                    s[ri][1] += q * k4.y;
                    s[ri][2] += q * k4.z;
                    s[ri][3] += q * k4.w;
                }
            }
        }

        // scale + causal mask on diagonal tile
        #pragma unroll
        for (int ri = 0; ri < 4; ri++) {
            int ig = i0 + rgrp * 4 + ri;
            #pragma unroll
            for (int jj = 0; jj < 4; jj++) {
                int jg = j0 + cgrp * 4 + jj;
                s[ri][jj] = (jg > ig) ? -1e30f : s[ri][jj] * 0.125f;
            }
        }

        // online softmax update (row reductions over 16 lanes via shfl)
        float p[4][4];
        #pragma unroll
        for (int ri = 0; ri < 4; ri++) {
            float mt = fmaxf(fmaxf(s[ri][0], s[ri][1]),
                             fmaxf(s[ri][2], s[ri][3]));
            #pragma unroll
            for (int off = 1; off < 16; off <<= 1)
                mt = fmaxf(mt, __shfl_xor_sync(0xffffffffu, mt, off));
            float newm = fmaxf(m[ri], mt);
            float scale = __expf(m[ri] - newm);
            float rs = 0.f;
            #pragma unroll
            for (int jj = 0; jj < 4; jj++) {
                float e = __expf(s[ri][jj] - newm);
                p[ri][jj] = e;
                rs += e;
            }
            #pragma unroll
            for (int off = 1; off < 16; off <<= 1)
                rs += __shfl_xor_sync(0xffffffffu, rs, off);
            l[ri] = l[ri] * scale + rs;
            m[ri] = newm;
            #pragma unroll
            for (int dc = 0; dc < 4; dc++) o[ri][dc] *= scale;
        }

        __syncthreads();   // all warps done reading Kt before P overwrites it

        // write P into Kt's space as [r][j]
        #pragma unroll
        for (int ri = 0; ri < 4; ri++)
            *(float4*)&KtPs[(rgrp * 4 + ri) * 64 + cgrp * 4] =
                make_float4(p[ri][0], p[ri][1], p[ri][2], p[ri][3]);
        __syncthreads();

        // O += P V   (thread owns rows rgrp*4+ri, cols cgrp*4+dc)
        for (int jb = 0; jb < 64; jb += 4) {
            float4 p4[4];
            #pragma unroll
            for (int ri = 0; ri < 4; ri++)
                p4[ri] = *(const float4*)&KtPs[(rgrp * 4 + ri) * 64 + jb];
            #pragma unroll
            for (int jj = 0; jj < 4; jj++) {
                float4 v4 = *(const float4*)&Vs[(jb + jj) * 64 + cgrp * 4];
                #pragma unroll
                for (int ri = 0; ri < 4; ri++) {
                    float pv = (jj == 0) ? p4[ri].x : (jj == 1) ? p4[ri].y
                             : (jj == 2) ? p4[ri].z : p4[ri].w;
                    o[ri][0] += pv * v4.x;
                    o[ri][1] += pv * v4.y;
                    o[ri][2] += pv * v4.z;
                    o[ri][3] += pv * v4.w;
                }
            }
        }
    }

    // finalize
    #pragma unroll
    for (int ri = 0; ri < 4; ri++) {
        float inv = 1.0f / l[ri];
        int r = i0 + rgrp * 4 + ri;
        *(float4*)&g_attno[(tokBase + r) * Dz + h * HDz + cgrp * 4] =
            make_float4(o[ri][0] * inv, o[ri][1] * inv,
                        o[ri][2] * inv, o[ri][3] * inv);
    }
}

// ---------------------------------------------------------------------------
// Residual + LayerNorm: h = LN(h + r) * g + be   (in-place on g_h)
// ---------------------------------------------------------------------------
__global__ void residual_ln_kernel(const float* __restrict__ r,
                                   const float* __restrict__ g,
                                   const float* __restrict__ be) {
    int t = blockIdx.x;
    int tid = threadIdx.x;
    __shared__ float red[256];

    float v0 = g_h[(size_t)t * Dz + tid]       + r[(size_t)t * Dz + tid];
    float v1 = g_h[(size_t)t * Dz + tid + 256] + r[(size_t)t * Dz + tid + 256];

    float mu = block_reduce_sum_256(v0 + v1, red) * (1.0f / Dz);
    float d0 = v0 - mu, d1 = v1 - mu;
    float var = block_reduce_sum_256(d0 * d0 + d1 * d1, red) * (1.0f / Dz);
    float inv = rsqrtf(var + 1e-5f);

    g_h[(size_t)t * Dz + tid]       = d0 * inv * g[tid]       + be[tid];
    g_h[(size_t)t * Dz + tid + 256] = d1 * inv * g[tid + 256] + be[tid + 256];
}

// ---------------------------------------------------------------------------
// Head: logits = gelu(h_last @ w_h1 + b_h1) @ w_h2 + b_h2   (last token only)
// ---------------------------------------------------------------------------
__global__ void head_kernel(const float* __restrict__ w_h1,
                            const float* __restrict__ b_h1,
                            const float* __restrict__ w_h2,
                            const float* __restrict__ b_h2,
                            float* __restrict__ out) {
    int b = blockIdx.x;
    int tid = threadIdx.x;
    int t = b * Sz + (Sz - 1);
    __shared__ float hrow[Dz];
    __shared__ float mid[Dz / 2];

    hrow[tid]       = g_h[(size_t)t * Dz + tid];
    hrow[tid + 256] = g_h[(size_t)t * Dz + tid + 256];
    __syncthreads();

    float acc = b_h1[tid];
    #pragma unroll 8
    for (int k = 0; k < Dz; k++) acc += hrow[k] * w_h1[k * (Dz / 2) + tid];
    mid[tid] = gelu_exact(acc);
    __syncthreads();

    if (tid < OUTz) {
        float o = b_h2[tid];
        for (int j = 0; j < Dz / 2; j++) o += mid[j] * w_h2[j * OUTz + tid];
        out[b * OUTz + tid] = o;
    }
}

// ---------------------------------------------------------------------------
// Launch
// ---------------------------------------------------------------------------
extern "C" void kernel_launch(void* const* d_in, const int* in_sizes, int n_in,
                              void* d_out, int out_size) {
    const float* x     = (const float*)d_in[0];
    const float* w_in  = (const float*)d_in[1];
    const float* b_in  = (const float*)d_in[2];
    const float* g_in  = (const float*)d_in[3];
    const float* be_in = (const float*)d_in[4];
    const float* w_qkv = (const float*)d_in[5];
    const float* b_qkv = (const float*)d_in[6];
    const float* w_out = (const float*)d_in[7];
    const float* b_out = (const float*)d_in[8];
    const float* g1    = (const float*)d_in[9];
    const float* be1   = (const float*)d_in[10];
    const float* w_ff1 = (const float*)d_in[11];
    const float* b_ff1 = (const float*)d_in[12];
    const float* w_ff2 = (const float*)d_in[13];
    const float* b_ff2 = (const float*)d_in[14];
    const float* g2    = (const float*)d_in[15];
    const float* be2   = (const float*)d_in[16];
    const float* w_h1  = (const float*)d_in[17];
    const float* b_h1  = (const float*)d_in[18];
    const float* w_h2  = (const float*)d_in[19];
    const float* b_h2  = (const float*)d_in[20];
    float* out = (float*)d_out;

    static float *p_h = nullptr, *p_qkv = nullptr, *p_attno = nullptr,
                 *p_ff = nullptr, *p_res = nullptr;
    if (!p_h) {
        cudaGetSymbolAddress((void**)&p_h, g_h);
        cudaGetSymbolAddress((void**)&p_qkv, g_qkv);
        cudaGetSymbolAddress((void**)&p_attno, g_attno);
        cudaGetSymbolAddress((void**)&p_ff, g_ff);
        cudaGetSymbolAddress((void**)&p_res, g_res);
    }

    embed_kernel<<<BS, 256>>>(x, w_in, b_in, g_in, be_in);

    for (int l = 0; l < Lz; l++) {
        const float* wqkv_l = w_qkv + (size_t)l * Dz * 3 * Dz;
        const float* bqkv_l = b_qkv + (size_t)l * 3 * Dz;
        const float* wout_l = w_out + (size_t)l * Dz * Dz;
        const float* bout_l = b_out + (size_t)l * Dz;
        const float* wff1_l = w_ff1 + (size_t)l * Dz * FFz;
        const float* bff1_l = b_ff1 + (size_t)l * FFz;
        const float* wff2_l = w_ff2 + (size_t)l * FFz * Dz;
        const float* bff2_l = b_ff2 + (size_t)l * Dz;

        // qkv = h @ w_qkv + b
        sgemm_tc<0><<<dim3((3 * Dz) / TBN, BS / TBM), 256>>>(
            p_h, wqkv_l, bqkv_l, p_qkv, BS, 3 * Dz, Dz);

        // attention (flash-tiled)
        attn_flash_kernel<<<dim3(Sz / 64, Bz * Hz), 256>>>();

        // out projection
        sgemm_tc<0><<<dim3(Dz / TBN, BS / TBM), 256>>>(
            p_attno, wout_l, bout_l, p_res, BS, Dz, Dz);

        residual_ln_kernel<<<BS, 256>>>(p_res, g1 + (size_t)l * Dz,
                                        be1 + (size_t)l * Dz);

        // ff1 with gelu
        sgemm_tc<1><<<dim3(FFz / TBN, BS / TBM), 256>>>(
            p_h, wff1_l, bff1_l, p_ff, BS, FFz, Dz);

        // ff2
        sgemm_tc<0><<<dim3(Dz / TBN, BS / TBM), 256>>>(
            p_ff, wff2_l, bff2_l, p_res, BS, Dz, FFz);

        residual_ln_kernel<<<BS, 256>>>(p_res, g2 + (size_t)l * Dz,
                                        be2 + (size_t)l * Dz);
    }

    head_kernel<<<Bz, 256>>>(w_h1, b_h1, w_h2, b_h2, out);
}

// round 3
// speedup vs baseline: 5.3293x; 1.4058x over previous
#include <cuda_runtime.h>
#include <math.h>
#include <stdint.h>

// ---------------------------------------------------------------------------
// Problem constants
// ---------------------------------------------------------------------------
#define Bz  32
#define Sz  512
#define Dz  512
#define Hz  8
#define HDz 64
#define FFz 2048
#define Lz  6
#define INz 32
#define OUTz 3
#define BS  (Bz * Sz)          // 16384 tokens

// ---------------------------------------------------------------------------
// Scratch buffers (static device globals; no runtime allocation)
// ---------------------------------------------------------------------------
__device__ float g_h[BS * Dz];
__device__ float g_qkv[BS * 3 * Dz];
__device__ float g_attno[BS * Dz];
__device__ float g_ff[BS * FFz];
__device__ float g_res[BS * Dz];

// ---------------------------------------------------------------------------
// Helpers
// ---------------------------------------------------------------------------
__device__ __forceinline__ float gelu_exact(float x) {
    return 0.5f * x * (1.0f + erff(x * 0.70710678118654752f));
}

__device__ __forceinline__ uint32_t f2tf32(float x) {
    uint32_t u;
    asm("cvt.rna.tf32.f32 %0, %1;" : "=r"(u) : "f"(x));
    return u;
}

__device__ __forceinline__ void cp_async16(void* smem_dst, const void* gmem_src) {
    uint32_t s = (uint32_t)__cvta_generic_to_shared(smem_dst);
    asm volatile("cp.async.ca.shared.global [%0], [%1], 16;" :: "r"(s), "l"(gmem_src));
}
#define CP_COMMIT()  asm volatile("cp.async.commit_group;")
#define CP_WAIT1()   asm volatile("cp.async.wait_group 1;")

__device__ __forceinline__ void mma_tf32(float* c, const uint32_t* a, const uint32_t* b) {
    asm volatile(
        "mma.sync.aligned.m16n8k8.row.col.f32.tf32.tf32.f32 "
        "{%0,%1,%2,%3},{%4,%5,%6,%7},{%8,%9},{%0,%1,%2,%3};"
        : "+f"(c[0]), "+f"(c[1]), "+f"(c[2]), "+f"(c[3])
        : "r"(a[0]), "r"(a[1]), "r"(a[2]), "r"(a[3]), "r"(b[0]), "r"(b[1]));
}

__device__ __forceinline__ float block_reduce_sum_256(float v, float* red) {
    int tid = threadIdx.x;
    red[tid] = v;
    __syncthreads();
    #pragma unroll
    for (int s = 128; s > 0; s >>= 1) {
        if (tid < s) red[tid] += red[tid + s];
        __syncthreads();
    }
    float r = red[0];
    __syncthreads();
    return r;
}

// ---------------------------------------------------------------------------
// Embed: h = gelu(LN(x @ w_in + b_in)) + PE
// ---------------------------------------------------------------------------
__global__ void embed_kernel(const float* __restrict__ x,
                             const float* __restrict__ w_in,
                             const float* __restrict__ b_in,
                             const float* __restrict__ g_in,
                             const float* __restrict__ be_in) {
    int t = blockIdx.x;
    int tid = threadIdx.x;
    __shared__ float xrow[INz];
    __shared__ float vals[Dz];
    __shared__ float red[256];

    if (tid < INz) xrow[tid] = x[t * INz + tid];
    __syncthreads();

    #pragma unroll
    for (int p = 0; p < 2; p++) {
        int c = tid + p * 256;
        float acc = b_in[c];
        #pragma unroll
        for (int k = 0; k < INz; k++) acc += xrow[k] * w_in[k * Dz + c];
        vals[c] = acc;
    }
    __syncthreads();

    float v0 = vals[tid], v1 = vals[tid + 256];
    float mu = block_reduce_sum_256(v0 + v1, red) * (1.0f / Dz);
    float d0 = v0 - mu, d1 = v1 - mu;
    float var = block_reduce_sum_256(d0 * d0 + d1 * d1, red) * (1.0f / Dz);
    float inv = rsqrtf(var + 1e-5f);

    int s = t % Sz;
    float pos = (float)s;
    const float kLog = 9.210340371976184f / (float)Dz;

    #pragma unroll
    for (int p = 0; p < 2; p++) {
        int c = tid + p * 256;
        float d = (p == 0 ? d0 : d1);
        float y = d * inv * g_in[c] + be_in[c];
        y = gelu_exact(y);
        int i2 = c & ~1;
        float div = __expf(-(float)i2 * kLog);
        float ang = pos * div;
        y += (c & 1) ? cosf(ang) : sinf(ang);
        g_h[t * Dz + c] = y;
    }
}

// ---------------------------------------------------------------------------
// TF32 tensor-core GEMM with 2-stage cp.async pipeline.
// 128x128x16 CTA tile, 256 threads (8 warps), warp = 64x32 via m16n8k8.
// As: [m][k] stride 20 (conflict-free A-frags); Bs: [k][n] stride 136.
// ---------------------------------------------------------------------------
#define TBM 128
#define TBN 128
#define TBK 16
#define AST 20
#define BST 136

template <int ACT>
__global__ __launch_bounds__(256, 2)
void sgemm_tc(const float* __restrict__ A,
              const float* __restrict__ W,
              const float* __restrict__ bias,
              float* __restrict__ C,
              int M, int N, int K) {
    __shared__ float As[2][TBM * AST];
    __shared__ float Bs[2][TBK * BST];

    int tid = threadIdx.x;
    int lane = tid & 31;
    int wid = tid >> 5;
    int wm = wid >> 2;
    int wn = wid & 3;
    int qk = lane & 3;
    int qr = lane >> 2;

    int rowBase = blockIdx.y * TBM;
    int colBase = blockIdx.x * TBN;

    // staging indices
    int s_ar = tid >> 1;                 // A: 256 chunks of 16B per half
    int s_ac = (tid & 1) << 3;           // (placeholder; real mapping below)
    (void)s_ar; (void)s_ac;

    float acc[4][4][4];
    #pragma unroll
    for (int i = 0; i < 4; i++)
        #pragma unroll
        for (int j = 0; j < 4; j++)
            #pragma unroll
            for (int c = 0; c < 4; c++) acc[i][j][c] = 0.f;

    int nk = K / TBK;

    auto stage = [&](int buf, int k0) {
        // A tile: 128 rows x 16 k = 512 float4 chunks
        #pragma unroll
        for (int p = 0; p < 2; p++) {
            int c = tid + p * 256;
            int row = c >> 2;
            int kc = (c & 3) << 2;
            cp_async16(&As[buf][row * AST + kc],
                       A + (size_t)(rowBase + row) * K + k0 + kc);
        }
        // B tile: 16 k x 128 n = 512 float4 chunks
        #pragma unroll
        for (int p = 0; p < 2; p++) {
            int c = tid + p * 256;
            int kr = c >> 5;
            int nc = (c & 31) << 2;
            cp_async16(&Bs[buf][kr * BST + nc],
                       W + (size_t)(k0 + kr) * N + colBase + nc);
        }
    };

    stage(0, 0);
    CP_COMMIT();

    for (int kt = 0; kt < nk; kt++) {
        if (kt + 1 < nk) stage((kt + 1) & 1, (kt + 1) * TBK);
        CP_COMMIT();
        CP_WAIT1();
        __syncthreads();

        const float* Ab = As[kt & 1];
        const float* Bb = Bs[kt & 1];

        #pragma unroll
        for (int ks = 0; ks < TBK; ks += 8) {
            uint32_t af[4][4], bf[4][2];
            #pragma unroll
            for (int mt = 0; mt < 4; mt++) {
                int mb = wm * 64 + mt * 16 + qr;
                af[mt][0] = f2tf32(Ab[mb * AST + ks + qk]);
                af[mt][1] = f2tf32(Ab[(mb + 8) * AST + ks + qk]);
                af[mt][2] = f2tf32(Ab[mb * AST + ks + qk + 4]);
                af[mt][3] = f2tf32(Ab[(mb + 8) * AST + ks + qk + 4]);
            }
            #pragma unroll
            for (int nt = 0; nt < 4; nt++) {
                int nbb = wn * 32 + nt * 8 + qr;
                bf[nt][0] = f2tf32(Bb[(ks + qk) * BST + nbb]);
                bf[nt][1] = f2tf32(Bb[(ks + qk + 4) * BST + nbb]);
            }
            #pragma unroll
            for (int mt = 0; mt < 4; mt++)
                #pragma unroll
                for (int nt = 0; nt < 4; nt++)
                    mma_tf32(acc[mt][nt], af[mt], bf[nt]);
        }
        __syncthreads();
    }

    #pragma unroll
    for (int mt = 0; mt < 4; mt++) {
        int row0 = rowBase + wm * 64 + mt * 16 + qr;
        #pragma unroll
        for (int nt = 0; nt < 4; nt++) {
            int col0 = colBase + wn * 32 + nt * 8 + 2 * qk;
            float bia0 = bias[col0], bia1 = bias[col0 + 1];
            float v0 = acc[mt][nt][0] + bia0;
            float v1 = acc[mt][nt][1] + bia1;
            float v2 = acc[mt][nt][2] + bia0;
            float v3 = acc[mt][nt][3] + bia1;
            if (ACT == 1) {
                v0 = gelu_exact(v0); v1 = gelu_exact(v1);
                v2 = gelu_exact(v2); v3 = gelu_exact(v3);
            }
            *(float2*)&C[(size_t)row0 * N + col0] = make_float2(v0, v1);
            *(float2*)&C[(size_t)(row0 + 8) * N + col0] = make_float2(v2, v3);
        }
    }
}

// ---------------------------------------------------------------------------
// Tensor-core flash attention. Block = (64-query tile, b*H+h), 128 threads
// (4 warps), warp owns 16 rows x 64 cols. No K transpose: B-fragments for
// S = Q K^T read row-major K[j][d] directly (stride 68 = conflict-free).
// Q fragments in registers (pre-scaled, tf32). P aliases K's smem.
// ---------------------------------------------------------------------------
#define KST 68   // Ks / Ps stride (4 mod 32)
#define VST 72   // Vs stride (8 mod 32)

__global__ __launch_bounds__(128, 4)
void attn_flash_tc() {
    __shared__ float KsPs[64 * KST];   // K[j][d]; later P[r][j]
    __shared__ float Vs[64 * VST];     // V[j][d]

    int itile = blockIdx.x;
    int bh = blockIdx.y;
    int b = bh / Hz;
    int h = bh % Hz;
    int tid = threadIdx.x;
    int lane = tid & 31;
    int wid = tid >> 5;
    int qk = lane & 3;
    int qr = lane >> 2;
    int rbase = wid * 16;
    int i0 = itile * 64;
    size_t tokBase = (size_t)b * Sz;

    // Q fragments: rows rbase+qr / +8, k = d. Pre-scale by 1/8, cvt tf32.
    uint32_t qf[8][4];
    {
        const float* qbase = g_qkv + (tokBase + i0) * (3 * Dz) + h * HDz;
        int r0 = rbase + qr;
        #pragma unroll
        for (int ks = 0; ks < 8; ks++) {
            int d0 = ks * 8 + qk;
            qf[ks][0] = f2tf32(0.125f * qbase[(size_t)r0 * (3 * Dz) + d0]);
            qf[ks][1] = f2tf32(0.125f * qbase[(size_t)(r0 + 8) * (3 * Dz) + d0]);
            qf[ks][2] = f2tf32(0.125f * qbase[(size_t)r0 * (3 * Dz) + d0 + 4]);
            qf[ks][3] = f2tf32(0.125f * qbase[(size_t)(r0 + 8) * (3 * Dz) + d0 + 4]);
        }
    }

    float m0 = -1e30f, m1 = -1e30f, l0 = 0.f, l1 = 0.f;
    float o[8][4];
    #pragma unroll
    for (int dt = 0; dt < 8; dt++)
        #pragma unroll
        for (int c = 0; c < 4; c++) o[dt][c] = 0.f;

    for (int jt = 0; jt <= itile; jt++) {
        int j0 = jt * 64;
        __syncthreads();   // prior Ps/Vs readers done before overwrite

        // Stage K and V tiles (tf32-converted), row-major [j][d]
        #pragma unroll
        for (int it = 0; it < 8; it++) {
            int idx = tid + it * 128;        // 1024 chunks
            int j = idx >> 4;
            int dq = (idx & 15) << 2;
            const float* base = g_qkv + (tokBase + j0 + j) * (3 * Dz) + h * HDz;
            float4 k4 = *(const float4*)(base + Dz + dq);
            float4 v4 = *(const float4*)(base + 2 * Dz + dq);
            float4 kc, vc;
            kc.x = __uint_as_float(f2tf32(k4.x));
            kc.y = __uint_as_float(f2tf32(k4.y));
            kc.z = __uint_as_float(f2tf32(k4.z));
            kc.w = __uint_as_float(f2tf32(k4.w));
            vc.x = __uint_as_float(f2tf32(v4.x));
            vc.y = __uint_as_float(f2tf32(v4.y));
            vc.z = __uint_as_float(f2tf32(v4.z));
            vc.w = __uint_as_float(f2tf32(v4.w));
            *(float4*)&KsPs[j * KST + dq] = kc;
            *(float4*)&Vs[j * VST + dq] = vc;
        }
        __syncthreads();

        // S = Q K^T (already scaled). Accumulate over 8 k-steps.
        float s[8][4];
        #pragma unroll
        for (int nt = 0; nt < 8; nt++)
            #pragma unroll
            for (int c = 0; c < 4; c++) s[nt][c] = 0.f;

        #pragma unroll
        for (int ks = 0; ks < 8; ks++) {
            int d0 = ks * 8 + qk;
            #pragma unroll
            for (int nt = 0; nt < 8; nt++) {
                uint32_t bf[2];
                int jrow = nt * 8 + qr;
                bf[0] = __float_as_uint(KsPs[jrow * KST + d0]);
                bf[1] = __float_as_uint(KsPs[jrow * KST + d0 + 4]);
                mma_tf32(s[nt], qf[ks], bf);
            }
        }

        // causal mask on diagonal tile
        if (jt == itile) {
            int r0 = rbase + qr;
            #pragma unroll
            for (int nt = 0; nt < 8; nt++) {
                int j = nt * 8 + 2 * qk;
                if (j > r0)     s[nt][0] = -1e30f;
                if (j + 1 > r0) s[nt][1] = -1e30f;
                if (j > r0 + 8)     s[nt][2] = -1e30f;
                if (j + 1 > r0 + 8) s[nt][3] = -1e30f;
            }
        }

        // online softmax: rows r0 (c0,c1) and r0+8 (c2,c3)
        float mx0 = -1e30f, mx1 = -1e30f;
        #pragma unroll
        for (int nt = 0; nt < 8; nt++) {
            mx0 = fmaxf(mx0, fmaxf(s[nt][0], s[nt][1]));
            mx1 = fmaxf(mx1, fmaxf(s[nt][2], s[nt][3]));
        }
        mx0 = fmaxf(mx0, __shfl_xor_sync(0xffffffffu, mx0, 1));
        mx0 = fmaxf(mx0, __shfl_xor_sync(0xffffffffu, mx0, 2));
        mx1 = fmaxf(mx1, __shfl_xor_sync(0xffffffffu, mx1, 1));
        mx1 = fmaxf(mx1, __shfl_xor_sync(0xffffffffu, mx1, 2));

        float nm0 = fmaxf(m0, mx0);
        float nm1 = fmaxf(m1, mx1);
        float e0 = __expf(m0 - nm0);
        float e1 = __expf(m1 - nm1);

        float rs0 = 0.f, rs1 = 0.f;
        #pragma unroll
        for (int nt = 0; nt < 8; nt++) {
            s[nt][0] = __expf(s[nt][0] - nm0);
            s[nt][1] = __expf(s[nt][1] - nm0);
            s[nt][2] = __expf(s[nt][2] - nm1);
            s[nt][3] = __expf(s[nt][3] - nm1);
            rs0 += s[nt][0] + s[nt][1];
            rs1 += s[nt][2] + s[nt][3];
        }
        rs0 += __shfl_xor_sync(0xffffffffu, rs0, 1);
        rs0 += __shfl_xor_sync(0xffffffffu, rs0, 2);
        rs1 += __shfl_xor_sync(0xffffffffu, rs1, 1);
        rs1 += __shfl_xor_sync(0xffffffffu, rs1, 2);

        l0 = l0 * e0 + rs0;
        l1 = l1 * e1 + rs1;
        m0 = nm0;
        m1 = nm1;
        #pragma unroll
        for (int dt = 0; dt < 8; dt++) {
            o[dt][0] *= e0; o[dt][1] *= e0;
            o[dt][2] *= e1; o[dt][3] *= e1;
        }

        __syncthreads();   // all warps done reading Ks before P overwrite

        // Write P into Ps[r][j] (stride 68), tf32
        {
            int r0 = rbase + qr;
            #pragma unroll
            for (int nt = 0; nt < 8; nt++) {
                int j = nt * 8 + 2 * qk;
                float2 p01, p23;
                p01.x = __uint_as_float(f2tf32(s[nt][0]));
                p01.y = __uint_as_float(f2tf32(s[nt][1]));
                p23.x = __uint_as_float(f2tf32(s[nt][2]));
                p23.y = __uint_as_float(f2tf32(s[nt][3]));
                *(float2*)&KsPs[r0 * KST + j] = p01;
                *(float2*)&KsPs[(r0 + 8) * KST + j] = p23;
            }
        }
        __syncthreads();

        // O += P V : A = P[r][j] (stride 68), B = V[j][d] (stride 72)
        #pragma unroll
        for (int kj = 0; kj < 8; kj++) {
            uint32_t af[4];
            int r0 = rbase + qr;
            int jj = kj * 8 + qk;
            af[0] = __float_as_uint(KsPs[r0 * KST + jj]);
            af[1] = __float_as_uint(KsPs[(r0 + 8) * KST + jj]);
            af[2] = __float_as_uint(KsPs[r0 * KST + jj + 4]);
            af[3] = __float_as_uint(KsPs[(r0 + 8) * KST + jj + 4]);
            #pragma unroll
            for (int dt = 0; dt < 8; dt++) {
                uint32_t bf[2];
                int dn = dt * 8 + qr;
                bf[0] = __float_as_uint(Vs[jj * VST + dn]);
                bf[1] = __float_as_uint(Vs[(jj + 4) * VST + dn]);
                mma_tf32(o[dt], af, bf);
            }
        }
    }

    // finalize: divide by l, write out
    float inv0 = 1.0f / l0;
    float inv1 = 1.0f / l1;
    int r0 = i0 + rbase + qr;
    float* ob0 = g_attno + (tokBase + r0) * Dz + h * HDz;
    float* ob1 = g_attno + (tokBase + r0 + 8) * Dz + h * HDz;
    #pragma unroll
    for (int dt = 0; dt < 8; dt++) {
        int d = dt * 8 + 2 * qk;
        *(float2*)(ob0 + d) = make_float2(o[dt][0] * inv0, o[dt][1] * inv0);
        *(float2*)(ob1 + d) = make_float2(o[dt][2] * inv1, o[dt][3] * inv1);
    }
}

// ---------------------------------------------------------------------------
// Residual + LayerNorm
// ---------------------------------------------------------------------------
__global__ void residual_ln_kernel(const float* __restrict__ r,
                                   const float* __restrict__ g,
                                   const float* __restrict__ be) {
    int t = blockIdx.x;
    int tid = threadIdx.x;
    __shared__ float red[256];

    float v0 = g_h[(size_t)t * Dz + tid]       + r[(size_t)t * Dz + tid];
    float v1 = g_h[(size_t)t * Dz + tid + 256] + r[(size_t)t * Dz + tid + 256];

    float mu = block_reduce_sum_256(v0 + v1, red) * (1.0f / Dz);
    float d0 = v0 - mu, d1 = v1 - mu;
    float var = block_reduce_sum_256(d0 * d0 + d1 * d1, red) * (1.0f / Dz);
    float inv = rsqrtf(var + 1e-5f);

    g_h[(size_t)t * Dz + tid]       = d0 * inv * g[tid]       + be[tid];
    g_h[(size_t)t * Dz + tid + 256] = d1 * inv * g[tid + 256] + be[tid + 256];
}

// ---------------------------------------------------------------------------
// Head
// ---------------------------------------------------------------------------
__global__ void head_kernel(const float* __restrict__ w_h1,
                            const float* __restrict__ b_h1,
                            const float* __restrict__ w_h2,
                            const float* __restrict__ b_h2,
                            float* __restrict__ out) {
    int b = blockIdx.x;
    int tid = threadIdx.x;
    int t = b * Sz + (Sz - 1);
    __shared__ float hrow[Dz];
    __shared__ float mid[Dz / 2];

    hrow[tid]       = g_h[(size_t)t * Dz + tid];
    hrow[tid + 256] = g_h[(size_t)t * Dz + tid + 256];
    __syncthreads();

    float acc = b_h1[tid];
    #pragma unroll 8
    for (int k = 0; k < Dz; k++) acc += hrow[k] * w_h1[k * (Dz / 2) + tid];
    mid[tid] = gelu_exact(acc);
    __syncthreads();

    if (tid < OUTz) {
        float o = b_h2[tid];
        for (int j = 0; j < Dz / 2; j++) o += mid[j] * w_h2[j * OUTz + tid];
        out[b * OUTz + tid] = o;
    }
}

// ---------------------------------------------------------------------------
// Launch
// ---------------------------------------------------------------------------
extern "C" void kernel_launch(void* const* d_in, const int* in_sizes, int n_in,
                              void* d_out, int out_size) {
    const float* x     = (const float*)d_in[0];
    const float* w_in  = (const float*)d_in[1];
    const float* b_in  = (const float*)d_in[2];
    const float* g_in  = (const float*)d_in[3];
    const float* be_in = (const float*)d_in[4];
    const float* w_qkv = (const float*)d_in[5];
    const float* b_qkv = (const float*)d_in[6];
    const float* w_out = (const float*)d_in[7];
    const float* b_out = (const float*)d_in[8];
    const float* g1    = (const float*)d_in[9];
    const float* be1   = (const float*)d_in[10];
    const float* w_ff1 = (const float*)d_in[11];
    const float* b_ff1 = (const float*)d_in[12];
    const float* w_ff2 = (const float*)d_in[13];
    const float* b_ff2 = (const float*)d_in[14];
    const float* g2    = (const float*)d_in[15];
    const float* be2   = (const float*)d_in[16];
    const float* w_h1  = (const float*)d_in[17];
    const float* b_h1  = (const float*)d_in[18];
    const float* w_h2  = (const float*)d_in[19];
    const float* b_h2  = (const float*)d_in[20];
    float* out = (float*)d_out;

    static float *p_h = nullptr, *p_qkv = nullptr, *p_attno = nullptr,
                 *p_ff = nullptr, *p_res = nullptr;
    if (!p_h) {
        cudaGetSymbolAddress((void**)&p_h, g_h);
        cudaGetSymbolAddress((void**)&p_qkv, g_qkv);
        cudaGetSymbolAddress((void**)&p_attno, g_attno);
        cudaGetSymbolAddress((void**)&p_ff, g_ff);
        cudaGetSymbolAddress((void**)&p_res, g_res);
    }

    embed_kernel<<<BS, 256>>>(x, w_in, b_in, g_in, be_in);

    for (int l = 0; l < Lz; l++) {
        const float* wqkv_l = w_qkv + (size_t)l * Dz * 3 * Dz;
        const float* bqkv_l = b_qkv + (size_t)l * 3 * Dz;
        const float* wout_l = w_out + (size_t)l * Dz * Dz;
        const float* bout_l = b_out + (size_t)l * Dz;
        const float* wff1_l = w_ff1 + (size_t)l * Dz * FFz;
        const float* bff1_l = b_ff1 + (size_t)l * FFz;
        const float* wff2_l = w_ff2 + (size_t)l * FFz * Dz;
        const float* bff2_l = b_ff2 + (size_t)l * Dz;

        sgemm_tc<0><<<dim3((3 * Dz) / TBN, BS / TBM), 256>>>(
            p_h, wqkv_l, bqkv_l, p_qkv, BS, 3 * Dz, Dz);

        attn_flash_tc<<<dim3(Sz / 64, Bz * Hz), 128>>>();

        sgemm_tc<0><<<dim3(Dz / TBN, BS / TBM), 256>>>(
            p_attno, wout_l, bout_l, p_res, BS, Dz, Dz);

        residual_ln_kernel<<<BS, 256>>>(p_res, g1 + (size_t)l * Dz,
                                        be1 + (size_t)l * Dz);

        sgemm_tc<1><<<dim3(FFz / TBN, BS / TBM), 256>>>(
            p_h, wff1_l, bff1_l, p_ff, BS, FFz, Dz);

        sgemm_tc<0><<<dim3(Dz / TBN, BS / TBM), 256>>>(
            p_ff, wff2_l, bff2_l, p_res, BS, Dz, FFz);

        residual_ln_kernel<<<BS, 256>>>(p_res, g2 + (size_t)l * Dz,
                                        be2 + (size_t)l * Dz);
    }

    head_kernel<<<Bz, 256>>>(w_h1, b_h1, w_h2, b_h2, out);
}

// round 5
// speedup vs baseline: 5.4119x; 1.0155x over previous
#include <cuda_runtime.h>
#include <math.h>
#include <stdint.h>

// ---------------------------------------------------------------------------
// Problem constants
// ---------------------------------------------------------------------------
#define Bz  32
#define Sz  512
#define Dz  512
#define Hz  8
#define HDz 64
#define FFz 2048
#define Lz  6
#define INz 32
#define OUTz 3
#define BS  (Bz * Sz)

// ---------------------------------------------------------------------------
// Scratch buffers
// ---------------------------------------------------------------------------
__device__ float g_h[BS * Dz];
__device__ float g_qkv[BS * 3 * Dz];
__device__ float g_attno[BS * Dz];
__device__ float g_ff[BS * FFz];
__device__ float g_res[BS * Dz];

// ---------------------------------------------------------------------------
// Helpers
// ---------------------------------------------------------------------------
__device__ __forceinline__ float gelu_exact(float x) {
    return 0.5f * x * (1.0f + erff(x * 0.70710678118654752f));
}

__device__ __forceinline__ uint32_t f2tf32(float x) {
    uint32_t u;
    asm("cvt.rna.tf32.f32 %0, %1;" : "=r"(u) : "f"(x));
    return u;
}

__device__ __forceinline__ void cp_async16(void* smem_dst, const void* gmem_src) {
    uint32_t s = (uint32_t)__cvta_generic_to_shared(smem_dst);
    asm volatile("cp.async.ca.shared.global [%0], [%1], 16;" :: "r"(s), "l"(gmem_src));
}
#define CP_COMMIT()  asm volatile("cp.async.commit_group;")
#define CP_WAIT1()   asm volatile("cp.async.wait_group 1;")

__device__ __forceinline__ void mma_tf32(float* c, const uint32_t* a, const uint32_t* b) {
    asm volatile(
        "mma.sync.aligned.m16n8k8.row.col.f32.tf32.tf32.f32 "
        "{%0,%1,%2,%3},{%4,%5,%6,%7},{%8,%9},{%0,%1,%2,%3};"
        : "+f"(c[0]), "+f"(c[1]), "+f"(c[2]), "+f"(c[3])
        : "r"(a[0]), "r"(a[1]), "r"(a[2]), "r"(a[3]), "r"(b[0]), "r"(b[1]));
}

__device__ __forceinline__ float block_reduce_sum_256(float v, float* red) {
    int tid = threadIdx.x;
    red[tid] = v;
    __syncthreads();
    #pragma unroll
    for (int s = 128; s > 0; s >>= 1) {
        if (tid < s) red[tid] += red[tid + s];
        __syncthreads();
    }
    float r = red[0];
    __syncthreads();
    return r;
}

// ---------------------------------------------------------------------------
// Embed
// ---------------------------------------------------------------------------
__global__ void embed_kernel(const float* __restrict__ x,
                             const float* __restrict__ w_in,
                             const float* __restrict__ b_in,
                             const float* __restrict__ g_in,
                             const float* __restrict__ be_in) {
    int t = blockIdx.x;
    int tid = threadIdx.x;
    __shared__ float xrow[INz];
    __shared__ float vals[Dz];
    __shared__ float red[256];

    if (tid < INz) xrow[tid] = x[t * INz + tid];
    __syncthreads();

    #pragma unroll
    for (int p = 0; p < 2; p++) {
        int c = tid + p * 256;
        float acc = b_in[c];
        #pragma unroll
        for (int k = 0; k < INz; k++) acc += xrow[k] * w_in[k * Dz + c];
        vals[c] = acc;
    }
    __syncthreads();

    float v0 = vals[tid], v1 = vals[tid + 256];
    float mu = block_reduce_sum_256(v0 + v1, red) * (1.0f / Dz);
    float d0 = v0 - mu, d1 = v1 - mu;
    float var = block_reduce_sum_256(d0 * d0 + d1 * d1, red) * (1.0f / Dz);
    float inv = rsqrtf(var + 1e-5f);

    int s = t % Sz;
    float pos = (float)s;
    const float kLog = 9.210340371976184f / (float)Dz;

    #pragma unroll
    for (int p = 0; p < 2; p++) {
        int c = tid + p * 256;
        float d = (p == 0 ? d0 : d1);
        float y = d * inv * g_in[c] + be_in[c];
        y = gelu_exact(y);
        int i2 = c & ~1;
        float div = __expf(-(float)i2 * kLog);
        float ang = pos * div;
        y += (c & 1) ? cosf(ang) : sinf(ang);
        g_h[t * Dz + c] = y;
    }
}

// ---------------------------------------------------------------------------
// TF32 GEMM with 2-stage cp.async pipeline
// ---------------------------------------------------------------------------
#define TBM 128
#define TBN 128
#define TBK 16
#define AST 20
#define BST 136

template <int ACT>
__global__ __launch_bounds__(256, 2)
void sgemm_tc(const float* __restrict__ A,
              const float* __restrict__ W,
              const float* __restrict__ bias,
              float* __restrict__ C,
              int M, int N, int K) {
    __shared__ float As[2][TBM * AST];
    __shared__ float Bs[2][TBK * BST];

    int tid = threadIdx.x;
    int lane = tid & 31;
    int wid = tid >> 5;
    int wm = wid >> 2;
    int wn = wid & 3;
    int qk = lane & 3;
    int qr = lane >> 2;

    int rowBase = blockIdx.y * TBM;
    int colBase = blockIdx.x * TBN;

    float acc[4][4][4];
    #pragma unroll
    for (int i = 0; i < 4; i++)
        #pragma unroll
        for (int j = 0; j < 4; j++)
            #pragma unroll
            for (int c = 0; c < 4; c++) acc[i][j][c] = 0.f;

    int nk = K / TBK;

    auto stage = [&](int buf, int k0) {
        #pragma unroll
        for (int p = 0; p < 2; p++) {
            int c = tid + p * 256;
            int row = c >> 2;
            int kc = (c & 3) << 2;
            cp_async16(&As[buf][row * AST + kc],
                       A + (size_t)(rowBase + row) * K + k0 + kc);
        }
        #pragma unroll
        for (int p = 0; p < 2; p++) {
            int c = tid + p * 256;
            int kr = c >> 5;
            int nc = (c & 31) << 2;
            cp_async16(&Bs[buf][kr * BST + nc],
                       W + (size_t)(k0 + kr) * N + colBase + nc);
        }
    };

    stage(0, 0);
    CP_COMMIT();

    for (int kt = 0; kt < nk; kt++) {
        if (kt + 1 < nk) stage((kt + 1) & 1, (kt + 1) * TBK);
        CP_COMMIT();
        CP_WAIT1();
        __syncthreads();

        const float* Ab = As[kt & 1];
        const float* Bb = Bs[kt & 1];

        #pragma unroll
        for (int ks = 0; ks < TBK; ks += 8) {
            uint32_t af[4][4], bf[4][2];
            #pragma unroll
            for (int mt = 0; mt < 4; mt++) {
                int mb = wm * 64 + mt * 16 + qr;
                af[mt][0] = f2tf32(Ab[mb * AST + ks + qk]);
                af[mt][1] = f2tf32(Ab[(mb + 8) * AST + ks + qk]);
                af[mt][2] = f2tf32(Ab[mb * AST + ks + qk + 4]);
                af[mt][3] = f2tf32(Ab[(mb + 8) * AST + ks + qk + 4]);
            }
            #pragma unroll
            for (int nt = 0; nt < 4; nt++) {
                int nbb = wn * 32 + nt * 8 + qr;
                bf[nt][0] = f2tf32(Bb[(ks + qk) * BST + nbb]);
                bf[nt][1] = f2tf32(Bb[(ks + qk + 4) * BST + nbb]);
            }
            #pragma unroll
            for (int mt = 0; mt < 4; mt++)
                #pragma unroll
                for (int nt = 0; nt < 4; nt++)
                    mma_tf32(acc[mt][nt], af[mt], bf[nt]);
        }
        __syncthreads();
    }

    #pragma unroll
    for (int mt = 0; mt < 4; mt++) {
        int row0 = rowBase + wm * 64 + mt * 16 + qr;
        #pragma unroll
        for (int nt = 0; nt < 4; nt++) {
            int col0 = colBase + wn * 32 + nt * 8 + 2 * qk;
            float bia0 = bias[col0], bia1 = bias[col0 + 1];
            float v0 = acc[mt][nt][0] + bia0;
            float v1 = acc[mt][nt][1] + bia1;
            float v2 = acc[mt][nt][2] + bia0;
            float v3 = acc[mt][nt][3] + bia1;
            if (ACT == 1) {
                v0 = gelu_exact(v0); v1 = gelu_exact(v1);
                v2 = gelu_exact(v2); v3 = gelu_exact(v3);
            }
            *(float2*)&C[(size_t)row0 * N + col0] = make_float2(v0, v1);
            *(float2*)&C[(size_t)(row0 + 8) * N + col0] = make_float2(v2, v3);
        }
    }
}

// ---------------------------------------------------------------------------
// Tensor-core flash attention v2 (fixed staging):
//  - cp.async double-buffered K/V tiles (full 64x64 tiles: 1024 chunks each)
//  - P redistributed C-frag -> A-frag via register shuffles (no smem P)
// Block = (64-query tile, b*H+h), 128 threads (4 warps), warp = 16 rows.
// ---------------------------------------------------------------------------
#define KST 68
#define VST 72
#define ATTN_SMEM ((2 * 64 * KST + 2 * 64 * VST) * 4)

__global__ __launch_bounds__(128, 3)
void attn_flash_tc() {
    extern __shared__ float sm[];
    float* Kb[2] = { sm, sm + 64 * KST };
    float* Vb[2] = { sm + 2 * 64 * KST, sm + 2 * 64 * KST + 64 * VST };

    int itile = blockIdx.x;
    int bh = blockIdx.y;
    int b = bh / Hz;
    int h = bh % Hz;
    int tid = threadIdx.x;
    int lane = tid & 31;
    int wid = tid >> 5;
    int qk = lane & 3;
    int qr = lane >> 2;
    int rbase = wid * 16;
    int i0 = itile * 64;
    size_t tokBase = (size_t)b * Sz;

    // Q fragments (pre-scaled by 1/8, tf32)
    uint32_t qf[8][4];
    {
        const float* qbase = g_qkv + (tokBase + i0) * (3 * Dz) + h * HDz;
        int r0 = rbase + qr;
        #pragma unroll
        for (int ks = 0; ks < 8; ks++) {
            int d0 = ks * 8 + qk;
            qf[ks][0] = f2tf32(0.125f * qbase[(size_t)r0 * (3 * Dz) + d0]);
            qf[ks][1] = f2tf32(0.125f * qbase[(size_t)(r0 + 8) * (3 * Dz) + d0]);
            qf[ks][2] = f2tf32(0.125f * qbase[(size_t)r0 * (3 * Dz) + d0 + 4]);
            qf[ks][3] = f2tf32(0.125f * qbase[(size_t)(r0 + 8) * (3 * Dz) + d0 + 4]);
        }
    }

    // FIXED: full-tile staging — 1024 float4 chunks for each of K and V.
    auto stage = [&](int buf, int jt) {
        int j0 = jt * 64;
        #pragma unroll
        for (int it = 0; it < 8; it++) {
            int idx = tid + it * 128;        // 0..1023
            int j = idx >> 4;                // 0..63
            int dq = (idx & 15) << 2;        // 0..60
            const float* base = g_qkv + (tokBase + j0 + j) * (3 * Dz) + h * HDz;
            cp_async16(&Kb[buf][j * KST + dq], base + Dz + dq);
            cp_async16(&Vb[buf][j * VST + dq], base + 2 * Dz + dq);
        }
    };

    float m0 = -1e30f, m1 = -1e30f, l0 = 0.f, l1 = 0.f;
    float o[8][4];
    #pragma unroll
    for (int dt = 0; dt < 8; dt++)
        #pragma unroll
        for (int c = 0; c < 4; c++) o[dt][c] = 0.f;

    stage(0, 0);
    CP_COMMIT();

    for (int jt = 0; jt <= itile; jt++) {
        int buf = jt & 1;
        if (jt < itile) stage(buf ^ 1, jt + 1);
        CP_COMMIT();
        CP_WAIT1();
        __syncthreads();

        const float* Ks = Kb[buf];
        const float* Vs = Vb[buf];

        // S = Q K^T
        float s[8][4];
        #pragma unroll
        for (int nt = 0; nt < 8; nt++)
            #pragma unroll
            for (int c = 0; c < 4; c++) s[nt][c] = 0.f;

        #pragma unroll
        for (int ks = 0; ks < 8; ks++) {
            int d0 = ks * 8 + qk;
            #pragma unroll
            for (int nt = 0; nt < 8; nt++) {
                uint32_t bf[2];
                int jrow = nt * 8 + qr;
                bf[0] = f2tf32(Ks[jrow * KST + d0]);
                bf[1] = f2tf32(Ks[jrow * KST + d0 + 4]);
                mma_tf32(s[nt], qf[ks], bf);
            }
        }

        // causal mask (diagonal tile only)
        if (jt == itile) {
            int r0 = rbase + qr;
            #pragma unroll
            for (int nt = 0; nt < 8; nt++) {
                int j = nt * 8 + 2 * qk;
                if (j > r0)         s[nt][0] = -1e30f;
                if (j + 1 > r0)     s[nt][1] = -1e30f;
                if (j > r0 + 8)     s[nt][2] = -1e30f;
                if (j + 1 > r0 + 8) s[nt][3] = -1e30f;
            }
        }

        // online softmax
        float mx0 = -1e30f, mx1 = -1e30f;
        #pragma unroll
        for (int nt = 0; nt < 8; nt++) {
            mx0 = fmaxf(mx0, fmaxf(s[nt][0], s[nt][1]));
            mx1 = fmaxf(mx1, fmaxf(s[nt][2], s[nt][3]));
        }
        mx0 = fmaxf(mx0, __shfl_xor_sync(0xffffffffu, mx0, 1));
        mx0 = fmaxf(mx0, __shfl_xor_sync(0xffffffffu, mx0, 2));
        mx1 = fmaxf(mx1, __shfl_xor_sync(0xffffffffu, mx1, 1));
        mx1 = fmaxf(mx1, __shfl_xor_sync(0xffffffffu, mx1, 2));

        float nm0 = fmaxf(m0, mx0);
        float nm1 = fmaxf(m1, mx1);
        float e0 = __expf(m0 - nm0);
        float e1 = __expf(m1 - nm1);

        float rs0 = 0.f, rs1 = 0.f;
        #pragma unroll
        for (int nt = 0; nt < 8; nt++) {
            s[nt][0] = __expf(s[nt][0] - nm0);
            s[nt][1] = __expf(s[nt][1] - nm0);
            s[nt][2] = __expf(s[nt][2] - nm1);
            s[nt][3] = __expf(s[nt][3] - nm1);
            rs0 += s[nt][0] + s[nt][1];
            rs1 += s[nt][2] + s[nt][3];
        }
        rs0 += __shfl_xor_sync(0xffffffffu, rs0, 1);
        rs0 += __shfl_xor_sync(0xffffffffu, rs0, 2);
        rs1 += __shfl_xor_sync(0xffffffffu, rs1, 1);
        rs1 += __shfl_xor_sync(0xffffffffu, rs1, 2);

        l0 = l0 * e0 + rs0;
        l1 = l1 * e1 + rs1;
        m0 = nm0;
        m1 = nm1;
        #pragma unroll
        for (int dt = 0; dt < 8; dt++) {
            o[dt][0] *= e0; o[dt][1] *= e0;
            o[dt][2] *= e1; o[dt][3] *= e1;
        }

        // P: C-frag -> A-frag via shuffles, then O += P V
        int srcA = (lane & ~3) | (qk >> 1);
        int srcB = srcA + 2;
        bool odd = (qk & 1) != 0;
        #pragma unroll
        for (int nt = 0; nt < 8; nt++) {
            uint32_t p0 = f2tf32(s[nt][0]);
            uint32_t p1 = f2tf32(s[nt][1]);
            uint32_t p2 = f2tf32(s[nt][2]);
            uint32_t p3 = f2tf32(s[nt][3]);
            uint32_t af[4];
            uint32_t x, y;
            x = __shfl_sync(0xffffffffu, p0, srcA);
            y = __shfl_sync(0xffffffffu, p1, srcA);
            af[0] = odd ? y : x;
            x = __shfl_sync(0xffffffffu, p2, srcA);
            y = __shfl_sync(0xffffffffu, p3, srcA);
            af[1] = odd ? y : x;
            x = __shfl_sync(0xffffffffu, p0, srcB);
            y = __shfl_sync(0xffffffffu, p1, srcB);
            af[2] = odd ? y : x;
            x = __shfl_sync(0xffffffffu, p2, srcB);
            y = __shfl_sync(0xffffffffu, p3, srcB);
            af[3] = odd ? y : x;

            int jj = nt * 8 + qk;
            #pragma unroll
            for (int dt = 0; dt < 8; dt++) {
                uint32_t bf[2];
                int dn = dt * 8 + qr;
                bf[0] = f2tf32(Vs[jj * VST + dn]);
                bf[1] = f2tf32(Vs[(jj + 4) * VST + dn]);
                mma_tf32(o[dt], af, bf);
            }
        }
        __syncthreads();   // block done with buf before it is re-staged
    }

    float inv0 = 1.0f / l0;
    float inv1 = 1.0f / l1;
    int r0 = i0 + rbase + qr;
    float* ob0 = g_attno + (tokBase + r0) * Dz + h * HDz;
    float* ob1 = g_attno + (tokBase + r0 + 8) * Dz + h * HDz;
    #pragma unroll
    for (int dt = 0; dt < 8; dt++) {
        int d = dt * 8 + 2 * qk;
        *(float2*)(ob0 + d) = make_float2(o[dt][0] * inv0, o[dt][1] * inv0);
        *(float2*)(ob1 + d) = make_float2(o[dt][2] * inv1, o[dt][3] * inv1);
    }
}

// ---------------------------------------------------------------------------
// Residual + LayerNorm: 2 tokens per 256-thread block, float4 + shfl reduce
// ---------------------------------------------------------------------------
__global__ void residual_ln_kernel(const float* __restrict__ r,
                                   const float* __restrict__ g,
                                   const float* __restrict__ be) {
    int tok = blockIdx.x * 2 + (threadIdx.x >> 7);
    int c = (threadIdx.x & 127) << 2;
    size_t off = (size_t)tok * Dz + c;

    float4 hv = *(const float4*)&g_h[off];
    float4 rv = *(const float4*)&r[off];
    float x0 = hv.x + rv.x, x1 = hv.y + rv.y;
    float x2 = hv.z + rv.z, x3 = hv.w + rv.w;

    float s = x0 + x1 + x2 + x3;
    float q = x0 * x0 + x1 * x1 + x2 * x2 + x3 * x3;
    #pragma unroll
    for (int o2 = 16; o2 > 0; o2 >>= 1) {
        s += __shfl_xor_sync(0xffffffffu, s, o2);
        q += __shfl_xor_sync(0xffffffffu, q, o2);
    }

    __shared__ float ws[8][2];
    int w = threadIdx.x >> 5;
    if ((threadIdx.x & 31) == 0) { ws[w][0] = s; ws[w][1] = q; }
    __syncthreads();

    int wb = (threadIdx.x >> 7) << 2;
    s = ws[wb][0] + ws[wb + 1][0] + ws[wb + 2][0] + ws[wb + 3][0];
    q = ws[wb][1] + ws[wb + 1][1] + ws[wb + 2][1] + ws[wb + 3][1];

    float mu = s * (1.0f / Dz);
    float var = q * (1.0f / Dz) - mu * mu;
    float inv = rsqrtf(var + 1e-5f);

    float4 gv = *(const float4*)&g[c];
    float4 bv = *(const float4*)&be[c];
    float4 outv;
    outv.x = (x0 - mu) * inv * gv.x + bv.x;
    outv.y = (x1 - mu) * inv * gv.y + bv.y;
    outv.z = (x2 - mu) * inv * gv.z + bv.z;
    outv.w = (x3 - mu) * inv * gv.w + bv.w;
    *(float4*)&g_h[off] = outv;
}

// ---------------------------------------------------------------------------
// Head
// ---------------------------------------------------------------------------
__global__ void head_kernel(const float* __restrict__ w_h1,
                            const float* __restrict__ b_h1,
                            const float* __restrict__ w_h2,
                            const float* __restrict__ b_h2,
                            float* __restrict__ out) {
    int b = blockIdx.x;
    int tid = threadIdx.x;
    int t = b * Sz + (Sz - 1);
    __shared__ float hrow[Dz];
    __shared__ float mid[Dz / 2];

    hrow[tid]       = g_h[(size_t)t * Dz + tid];
    hrow[tid + 256] = g_h[(size_t)t * Dz + tid + 256];
    __syncthreads();

    float acc = b_h1[tid];
    #pragma unroll 8
    for (int k = 0; k < Dz; k++) acc += hrow[k] * w_h1[k * (Dz / 2) + tid];
    mid[tid] = gelu_exact(acc);
    __syncthreads();

    if (tid < OUTz) {
        float o = b_h2[tid];
        for (int j = 0; j < Dz / 2; j++) o += mid[j] * w_h2[j * OUTz + tid];
        out[b * OUTz + tid] = o;
    }
}

// ---------------------------------------------------------------------------
// Launch
// ---------------------------------------------------------------------------
extern "C" void kernel_launch(void* const* d_in, const int* in_sizes, int n_in,
                              void* d_out, int out_size) {
    const float* x     = (const float*)d_in[0];
    const float* w_in  = (const float*)d_in[1];
    const float* b_in  = (const float*)d_in[2];
    const float* g_in  = (const float*)d_in[3];
    const float* be_in = (const float*)d_in[4];
    const float* w_qkv = (const float*)d_in[5];
    const float* b_qkv = (const float*)d_in[6];
    const float* w_out = (const float*)d_in[7];
    const float* b_out = (const float*)d_in[8];
    const float* g1    = (const float*)d_in[9];
    const float* be1   = (const float*)d_in[10];
    const float* w_ff1 = (const float*)d_in[11];
    const float* b_ff1 = (const float*)d_in[12];
    const float* w_ff2 = (const float*)d_in[13];
    const float* b_ff2 = (const float*)d_in[14];
    const float* g2    = (const float*)d_in[15];
    const float* be2   = (const float*)d_in[16];
    const float* w_h1  = (const float*)d_in[17];
    const float* b_h1  = (const float*)d_in[18];
    const float* w_h2  = (const float*)d_in[19];
    const float* b_h2  = (const float*)d_in[20];
    float* out = (float*)d_out;

    static float *p_h = nullptr, *p_qkv = nullptr, *p_attno = nullptr,
                 *p_ff = nullptr, *p_res = nullptr;
    if (!p_h) {
        cudaGetSymbolAddress((void**)&p_h, g_h);
        cudaGetSymbolAddress((void**)&p_qkv, g_qkv);
        cudaGetSymbolAddress((void**)&p_attno, g_attno);
        cudaGetSymbolAddress((void**)&p_ff, g_ff);
        cudaGetSymbolAddress((void**)&p_res, g_res);
        cudaFuncSetAttribute(attn_flash_tc,
                             cudaFuncAttributeMaxDynamicSharedMemorySize,
                             ATTN_SMEM);
    }

    embed_kernel<<<BS, 256>>>(x, w_in, b_in, g_in, be_in);

    for (int l = 0; l < Lz; l++) {
        const float* wqkv_l = w_qkv + (size_t)l * Dz * 3 * Dz;
        const float* bqkv_l = b_qkv + (size_t)l * 3 * Dz;
        const float* wout_l = w_out + (size_t)l * Dz * Dz;
        const float* bout_l = b_out + (size_t)l * Dz;
        const float* wff1_l = w_ff1 + (size_t)l * Dz * FFz;
        const float* bff1_l = b_ff1 + (size_t)l * FFz;
        const float* wff2_l = w_ff2 + (size_t)l * FFz * Dz;
        const float* bff2_l = b_ff2 + (size_t)l * Dz;

        sgemm_tc<0><<<dim3((3 * Dz) / TBN, BS / TBM), 256>>>(
            p_h, wqkv_l, bqkv_l, p_qkv, BS, 3 * Dz, Dz);

        attn_flash_tc<<<dim3(Sz / 64, Bz * Hz), 128, ATTN_SMEM>>>();

        sgemm_tc<0><<<dim3(Dz / TBN, BS / TBM), 256>>>(
            p_attno, wout_l, bout_l, p_res, BS, Dz, Dz);

        residual_ln_kernel<<<BS / 2, 256>>>(p_res, g1 + (size_t)l * Dz,
                                            be1 + (size_t)l * Dz);

        sgemm_tc<1><<<dim3(FFz / TBN, BS / TBM), 256>>>(
            p_h, wff1_l, bff1_l, p_ff, BS, FFz, Dz);

        sgemm_tc<0><<<dim3(Dz / TBN, BS / TBM), 256>>>(
            p_ff, wff2_l, bff2_l, p_res, BS, Dz, FFz);

        residual_ln_kernel<<<BS / 2, 256>>>(p_res, g2 + (size_t)l * Dz,
                                            be2 + (size_t)l * Dz);
    }

    head_kernel<<<Bz, 256>>>(w_h1, b_h1, w_h2, b_h2, out);
}